// round 8
// baseline (speedup 1.0000x reference)
#include <cuda_runtime.h>
#include <math.h>

#define NB 2
#define NS 2048
#define ND 1024
#define NH 16
#define NDK 64

// Scratch: projected Q/K/V [B,S,D] fp32 (head h = cols h*64..h*64+63)
__device__ float g_Qp[NB * NS * ND];
__device__ float g_Kp[NB * NS * ND];
__device__ float g_Vp[NB * NS * ND];

// ---------------------------------------------------------------------------
// Helpers
// ---------------------------------------------------------------------------
__device__ __forceinline__ float warp_max(float v) {
#pragma unroll
    for (int off = 16; off > 0; off >>= 1)
        v = fmaxf(v, __shfl_xor_sync(0xffffffffu, v, off));
    return v;
}
__device__ __forceinline__ float warp_sum(float v) {
#pragma unroll
    for (int off = 16; off > 0; off >>= 1)
        v += __shfl_xor_sync(0xffffffffu, v, off);
    return v;
}
// Monotone float<->uint transform: u-order == float-order (finite values).
__device__ __forceinline__ unsigned f2mono(float f) {
    unsigned b = __float_as_uint(f);
    return (b & 0x80000000u) ? ~b : (b | 0x80000000u);
}
__device__ __forceinline__ float mono2f(unsigned u) {
    unsigned b = (u & 0x80000000u) ? (u ^ 0x80000000u) : ~u;
    return __uint_as_float(b);
}
// Packed dual-FMA: acc.{lo,hi} += a.{lo,hi} * b.{lo,hi}
__device__ __forceinline__ void ffma2(unsigned long long& acc,
                                      unsigned long long a,
                                      unsigned long long b) {
    asm("fma.rn.f32x2 %0, %1, %2, %0;" : "+l"(acc) : "l"(a), "l"(b));
}
// Duplicate a float into both halves of a packed f32x2
__device__ __forceinline__ unsigned long long dup2(float x) {
    unsigned long long r;
    asm("mov.b64 %0, {%1, %1};" : "=l"(r) : "f"(x));
    return r;
}
union F4U2 { float4 f; unsigned long long u[2]; float s[4]; };

// Insert one 32-candidate batch (one per lane, candidate at lane j has
// column colbase+j) into the warp-distributed top-32 list. Strict '>' keeps
// earliest (lowest column) on ties, matching jax.lax.top_k.
__device__ __forceinline__ void batch_insert(unsigned u, int colbase, int lane,
                                             unsigned& lu, int& li, unsigned& um)
{
    unsigned bal = __ballot_sync(0xffffffffu, u > um);
    while (bal) {
        const int src = __ffs(bal) - 1;
        bal &= bal - 1;
        const unsigned uv = __shfl_sync(0xffffffffu, u, src);
        if (uv > um) {                 // um warp-uniform -> uniform branch
            const int ml = __ffs(__ballot_sync(0xffffffffu, lu == um)) - 1;
            if (lane == ml) { lu = uv; li = colbase + src; }
            um = __reduce_min_sync(0xffffffffu, lu);
        }
    }
}

// ---------------------------------------------------------------------------
// Projection GEMM (FFMA2): C = relu(A @ W + bias), M=4096, N=K=1024, x3.
// BK=16, double-buffered smem, one __syncthreads per k-step. (unchanged)
// ---------------------------------------------------------------------------
__global__ __launch_bounds__(256, 2) void proj_kernel(
    const float* __restrict__ X0, const float* __restrict__ W0, const float* __restrict__ B0,
    const float* __restrict__ X1, const float* __restrict__ W1, const float* __restrict__ B1,
    const float* __restrict__ X2, const float* __restrict__ W2, const float* __restrict__ B2)
{
    const int N = ND, K = ND;
    const int z = blockIdx.z;
    const float* A    = (z == 0) ? X0 : (z == 1) ? X1 : X2;
    const float* W    = (z == 0) ? W0 : (z == 1) ? W1 : W2;
    const float* bias = (z == 0) ? B0 : (z == 1) ? B1 : B2;
    float* C          = (z == 0) ? g_Qp : (z == 1) ? g_Kp : g_Vp;

    __shared__ float As[2][16][128];
    __shared__ float Bs[2][16][128];

    const int tid = threadIdx.x;
    const int tx = tid & 15;
    const int ty = tid >> 4;
    const int brow = blockIdx.y * 128;
    const int bcol = blockIdx.x * 128;

    const int ar = tid >> 1;
    const int ak = (tid & 1) << 3;
    const int wr = tid >> 4;
    const int wc = (tid & 15) << 3;

    unsigned long long accp[8][4];
#pragma unroll
    for (int i = 0; i < 8; i++)
#pragma unroll
        for (int q = 0; q < 4; q++) accp[i][q] = 0ull;

    const float* Aptr = A + (size_t)(brow + ar) * K + ak;
    const float* Wptr = W + (size_t)wr * N + bcol + wc;

    float4 a0 = *(const float4*)(Aptr);
    float4 a1 = *(const float4*)(Aptr + 4);
    float4 w0 = *(const float4*)(Wptr);
    float4 w1 = *(const float4*)(Wptr + 4);

    int p = 0;
    for (int k0 = 0; k0 < K; k0 += 16) {
        As[p][ak + 0][ar] = a0.x;
        As[p][ak + 1][ar] = a0.y;
        As[p][ak + 2][ar] = a0.z;
        As[p][ak + 3][ar] = a0.w;
        As[p][ak + 4][ar] = a1.x;
        As[p][ak + 5][ar] = a1.y;
        As[p][ak + 6][ar] = a1.z;
        As[p][ak + 7][ar] = a1.w;
        *(float4*)&Bs[p][wr][wc] = w0;
        *(float4*)&Bs[p][wr][wc + 4] = w1;
        __syncthreads();
        if (k0 + 16 < K) {
            a0 = *(const float4*)(Aptr + k0 + 16);
            a1 = *(const float4*)(Aptr + k0 + 20);
            w0 = *(const float4*)(Wptr + (size_t)(k0 + 16) * N);
            w1 = *(const float4*)(Wptr + (size_t)(k0 + 16) * N + 4);
        }
#pragma unroll
        for (int k = 0; k < 16; k++) {
            float4 av0 = *(const float4*)&As[p][k][ty * 4];
            float4 av1 = *(const float4*)&As[p][k][64 + ty * 4];
            F4U2 b0, b1;
            b0.f = *(const float4*)&Bs[p][k][tx * 4];
            b1.f = *(const float4*)&Bs[p][k][64 + tx * 4];
            unsigned long long bp[4] = {b0.u[0], b0.u[1], b1.u[0], b1.u[1]};
            float arr[8] = {av0.x, av0.y, av0.z, av0.w, av1.x, av1.y, av1.z, av1.w};
#pragma unroll
            for (int i = 0; i < 8; i++) {
                unsigned long long ad = dup2(arr[i]);
#pragma unroll
                for (int q = 0; q < 4; q++) ffma2(accp[i][q], ad, bp[q]);
            }
        }
        p ^= 1;
    }

#pragma unroll
    for (int i = 0; i < 8; i++) {
        const int r = brow + ((i < 4) ? (ty * 4 + i) : (64 + ty * 4 + (i - 4)));
        const float2* ap = (const float2*)&accp[i][0];
        {
            const int c = bcol + tx * 4;
            float4 v;
            v.x = fmaxf(ap[0].x + bias[c + 0], 0.0f);
            v.y = fmaxf(ap[0].y + bias[c + 1], 0.0f);
            v.z = fmaxf(ap[1].x + bias[c + 2], 0.0f);
            v.w = fmaxf(ap[1].y + bias[c + 3], 0.0f);
            *(float4*)(C + (size_t)r * N + c) = v;
        }
        {
            const int c = bcol + 64 + tx * 4;
            float4 v;
            v.x = fmaxf(ap[2].x + bias[c + 0], 0.0f);
            v.y = fmaxf(ap[2].y + bias[c + 1], 0.0f);
            v.z = fmaxf(ap[3].x + bias[c + 2], 0.0f);
            v.w = fmaxf(ap[3].y + bias[c + 3], 0.0f);
            *(float4*)(C + (size_t)r * N + c) = v;
        }
    }
}

// ---------------------------------------------------------------------------
// Fused score + top-32 select + softmax + V-gather.
// CTA = 128 q-rows of one (b,h). Loops over 32 column-chunks of 64:
//   [commit prefetched K chunk -> smem] [GEMM 128x64, FFMA2, same accumulation
//   order as before -> bit-identical scores] [mono-u32 scores -> smem]
//   [8 warps x 16 rows: online top-32 insert]  (K chunk c+1 LDG-prefetched
//   into registers before the select phase to hide DRAM latency).
// Tail: per row softmax over 32 survivors + V gather.
// Grid = (NS/128, NB*NH) = (16, 32). 2 CTAs/SM -> compute/select overlap.
// ---------------------------------------------------------------------------
#define FUSED_SMEM ((64 * 132 + 64 * 68) * 4 + 128 * 68 * 4)

__global__ __launch_bounds__(256, 2) void fused_kernel(float* __restrict__ out)
{
    extern __shared__ unsigned char smem_raw[];
    float*    As = (float*)smem_raw;           // [64][132]  Q^T tile (k-major)
    float*    Bs = As + 64 * 132;              // [64][68]   K^T chunk (k-major)
    unsigned* Ss = (unsigned*)(Bs + 64 * 68);  // [128][68]  chunk scores (mono)

    const int bh = blockIdx.y;
    const int b = bh >> 4, h = bh & 15;
    const int mrow = blockIdx.x * 128;
    const int tid = threadIdx.x;
    const int warp = tid >> 5, lane = tid & 31;
    const int tx = tid & 15, ty = tid >> 4;

    const float* Qb = g_Qp + (size_t)b * NS * ND + h * NDK;
    const float* Kb = g_Kp + (size_t)b * NS * ND + h * NDK;

    // ---- stage Q tile (once), transposed to As[k][m]
    {
        const int m = tid >> 1, kh = (tid & 1) * 32;
        const float4* qp = (const float4*)(Qb + (size_t)(mrow + m) * ND + kh);
        float4 q[8];
#pragma unroll
        for (int i = 0; i < 8; i++) q[i] = qp[i];
        const float* qs = (const float*)q;
#pragma unroll
        for (int j = 0; j < 32; j++) As[(kh + j) * 132 + m] = qs[j];
    }

    // ---- K chunk staging mapping: thread owns row kn, k-range kq*16..+16
    const int kn = tid & 63, kq = tid >> 6;
    float4 kst[4];
    {
        const float4* kp = (const float4*)(Kb + (size_t)kn * ND + kq * 16);
#pragma unroll
        for (int i = 0; i < 4; i++) kst[i] = kp[i];
    }

    // ---- per-row top-32 state (warp owns rows warp*16 .. +15)
    unsigned lu[16];
    int li[16];
    unsigned um[16];

    for (int c = 0; c < 32; ++c) {
        __syncthreads();                 // prev chunk fully consumed
        {   // commit prefetched K chunk to Bs[k][n]
            const float* ks = (const float*)kst;
#pragma unroll
            for (int j = 0; j < 16; j++) Bs[(kq * 16 + j) * 68 + kn] = ks[j];
        }
        __syncthreads();                 // Bs (and As on c==0) ready

        // GEMM: rows ty*8..+8, cols tx*4..+4 (acc packs col pairs; per-column
        // k-accumulation sequential 0..63 -> bit-identical to prior rounds)
        unsigned long long acc[8][2];
#pragma unroll
        for (int i = 0; i < 8; i++) { acc[i][0] = 0ull; acc[i][1] = 0ull; }
#pragma unroll 16
        for (int k = 0; k < 64; k++) {
            float4 a0 = *(const float4*)&As[k * 132 + ty * 8];
            float4 a1 = *(const float4*)&As[k * 132 + ty * 8 + 4];
            F4U2 bb;
            bb.f = *(const float4*)&Bs[k * 68 + tx * 4];
            float arr[8] = {a0.x, a0.y, a0.z, a0.w, a1.x, a1.y, a1.z, a1.w};
#pragma unroll
            for (int i = 0; i < 8; i++) {
                unsigned long long ad = dup2(arr[i]);
                ffma2(acc[i][0], ad, bb.u[0]);
                ffma2(acc[i][1], ad, bb.u[1]);
            }
        }

        // prefetch next K chunk into registers (consumed after next barrier;
        // DRAM latency hidden behind the select phase below)
        if (c < 31) {
            const float4* kp = (const float4*)(Kb + (size_t)((c + 1) * 64 + kn) * ND + kq * 16);
#pragma unroll
            for (int i = 0; i < 4; i++) kst[i] = kp[i];
        }

        // scores -> smem (scaled by 1/sqrt(64), mono-transformed)
#pragma unroll
        for (int i = 0; i < 8; i++) {
            const float2* ap = (const float2*)&acc[i][0];
            uint4 u;
            u.x = f2mono(ap[0].x * 0.125f);
            u.y = f2mono(ap[0].y * 0.125f);
            u.z = f2mono(ap[1].x * 0.125f);
            u.w = f2mono(ap[1].y * 0.125f);
            *(uint4*)&Ss[(ty * 8 + i) * 68 + tx * 4] = u;
        }
        __syncthreads();                 // Ss ready

        // select phase: batches in ascending column order (tie semantics)
        const int base = c * 64;
#pragma unroll
        for (int r = 0; r < 16; r++) {
            const int row = warp * 16 + r;
            const unsigned u0 = Ss[row * 68 + lane];
            const unsigned u1 = Ss[row * 68 + 32 + lane];
            if (c == 0) {
                lu[r] = u0;              // first 32 scores ARE the top-32
                li[r] = lane;
                um[r] = __reduce_min_sync(0xffffffffu, lu[r]);
            } else {
                batch_insert(u0, base, lane, lu[r], li[r], um[r]);
            }
            batch_insert(u1, base + 32, lane, lu[r], li[r], um[r]);
        }
    }

    // ---- tail: softmax over 32 survivors + V gather (exact fp32 values;
    // masked entries contribute exp(-1e9 - max) == 0 in fp32)
    const float* Vb = g_Vp + (size_t)b * NS * ND + h * NDK + lane * 2;
#pragma unroll
    for (int r = 0; r < 16; r++) {
        const float lval = mono2f(lu[r]);
        const float mx = warp_max(lval);
        const float e = __expf(lval - mx);
        const float w = e / warp_sum(e);

        float2 acc2 = make_float2(0.f, 0.f);
#pragma unroll
        for (int t = 0; t < 32; t++) {
            const int   vi = __shfl_sync(0xffffffffu, li[r], t);
            const float wt = __shfl_sync(0xffffffffu, w, t);
            const float2 v = *(const float2*)(Vb + (size_t)vi * ND);
            acc2.x += wt * v.x;
            acc2.y += wt * v.y;
        }
        const int row = mrow + warp * 16 + r;
        *(float2*)(out + (size_t)(b * NS + row) * ND + h * NDK + lane * 2) = acc2;
    }
}

// ---------------------------------------------------------------------------
extern "C" void kernel_launch(void* const* d_in, const int* in_sizes, int n_in,
                              void* d_out, int out_size)
{
    const float* query = (const float*)d_in[0];
    const float* key   = (const float*)d_in[1];
    const float* value = (const float*)d_in[2];
    const float* Wq    = (const float*)d_in[3];
    const float* bq    = (const float*)d_in[4];
    const float* Wk    = (const float*)d_in[5];
    const float* bk    = (const float*)d_in[6];
    const float* Wv    = (const float*)d_in[7];
    const float* bv    = (const float*)d_in[8];
    float* out = (float*)d_out;

    cudaFuncSetAttribute(fused_kernel,
                         cudaFuncAttributeMaxDynamicSharedMemorySize, FUSED_SMEM);

    dim3 pgrid(ND / 128, (NB * NS) / 128, 3);
    proj_kernel<<<pgrid, 256>>>(query, Wq, bq, key, Wk, bk, value, Wv, bv);

    dim3 fgrid(NS / 128, NB * NH);
    fused_kernel<<<fgrid, 256, FUSED_SMEM>>>(out);
}